// round 2
// baseline (speedup 1.0000x reference)
#include <cuda_runtime.h>

#define BATCH 2
#define SEQ   2048
#define HID   2048
#define NHEAD 16
#define DK    128
#define MROWS (BATCH*SEQ)

// Scratch (allocation-free per harness rules): q, k, v, attn_out
__device__ float g_q [(size_t)MROWS * HID];
__device__ float g_k [(size_t)MROWS * HID];
__device__ float g_v [(size_t)MROWS * HID];
__device__ float g_ao[(size_t)MROWS * HID];

// ---------------------------------------------------------------------------
// SGEMM (NT): C[m][n] = sum_k A[m][k] * B[n][k]
//   A: M x K row-major (K contiguous), B: N x K row-major (K contiguous)
// 128x128 block tile, BK=16, 256 threads, 8x8 per-thread micro-tile.
// Optional fused RoPE epilogue (do_rope=1): C holds q/k in (B,S,h,dk) layout,
// rotate even/odd pairs with freqs_cis[s][d/2][{cos,sin}].
// ---------------------------------------------------------------------------
__global__ __launch_bounds__(256)
void sgemm_nt(const float* __restrict__ A, const float* __restrict__ B,
              float* __restrict__ C, int K, int N,
              const float* __restrict__ freqs, int do_rope)
{
    __shared__ float As[16][132];
    __shared__ float Bs[16][132];

    const int t  = threadIdx.x;
    const int tx = t & 15;
    const int ty = t >> 4;
    const int rowBase = blockIdx.y * 128;
    const int colBase = blockIdx.x * 128;

    float acc[8][8];
    #pragma unroll
    for (int i = 0; i < 8; ++i)
        #pragma unroll
        for (int j = 0; j < 8; ++j) acc[i][j] = 0.f;

    const int lr = t >> 2;          // 0..63
    const int lk = (t & 3) << 2;    // 0,4,8,12
    const float* Ap = A + (size_t)(rowBase + lr) * K + lk;
    const float* Bp = B + (size_t)(colBase + lr) * K + lk;

    for (int k0 = 0; k0 < K; k0 += 16) {
        float4 a0 = *(const float4*)(Ap + k0);
        float4 a1 = *(const float4*)(Ap + (size_t)64 * K + k0);
        float4 b0 = *(const float4*)(Bp + k0);
        float4 b1 = *(const float4*)(Bp + (size_t)64 * K + k0);
        __syncthreads();   // previous compute done before overwriting smem
        As[lk+0][lr]    = a0.x; As[lk+1][lr]    = a0.y; As[lk+2][lr]    = a0.z; As[lk+3][lr]    = a0.w;
        As[lk+0][lr+64] = a1.x; As[lk+1][lr+64] = a1.y; As[lk+2][lr+64] = a1.z; As[lk+3][lr+64] = a1.w;
        Bs[lk+0][lr]    = b0.x; Bs[lk+1][lr]    = b0.y; Bs[lk+2][lr]    = b0.z; Bs[lk+3][lr]    = b0.w;
        Bs[lk+0][lr+64] = b1.x; Bs[lk+1][lr+64] = b1.y; Bs[lk+2][lr+64] = b1.z; Bs[lk+3][lr+64] = b1.w;
        __syncthreads();
        #pragma unroll
        for (int kk = 0; kk < 16; ++kk) {
            float4 af0 = *(const float4*)&As[kk][ty*8];
            float4 af1 = *(const float4*)&As[kk][ty*8+4];
            float4 bf0 = *(const float4*)&Bs[kk][tx*8];
            float4 bf1 = *(const float4*)&Bs[kk][tx*8+4];
            float ar[8] = {af0.x,af0.y,af0.z,af0.w,af1.x,af1.y,af1.z,af1.w};
            float br[8] = {bf0.x,bf0.y,bf0.z,bf0.w,bf1.x,bf1.y,bf1.z,bf1.w};
            #pragma unroll
            for (int i = 0; i < 8; ++i)
                #pragma unroll
                for (int j = 0; j < 8; ++j)
                    acc[i][j] = fmaf(ar[i], br[j], acc[i][j]);
        }
    }

    #pragma unroll
    for (int i = 0; i < 8; ++i) {
        const int grow = rowBase + ty*8 + i;
        float* Crow = C + (size_t)grow * N + colBase + tx*8;
        if (do_rope) {
            const int srow = grow & (SEQ - 1);            // m = b*S + s
            const float* fr = freqs + (size_t)srow * DK;  // (dk/2, 2) flattened
            #pragma unroll
            for (int jj = 0; jj < 8; jj += 2) {
                const int d = (colBase + tx*8 + jj) & (DK - 1);  // even
                const float cs = fr[d];
                const float sn = fr[d + 1];
                const float c0 = acc[i][jj], c1 = acc[i][jj+1];
                Crow[jj]   = c0*cs - c1*sn;
                Crow[jj+1] = c0*sn + c1*cs;
            }
        } else {
            *(float4*)(Crow)   = make_float4(acc[i][0],acc[i][1],acc[i][2],acc[i][3]);
            *(float4*)(Crow+4) = make_float4(acc[i][4],acc[i][5],acc[i][6],acc[i][7]);
        }
    }
}

// ---------------------------------------------------------------------------
// Flash attention, fp32, causal. One block per (q_tile of 64 rows, b*h).
// d_k = 128. smem: Qt/Kt transposed [128][68] (conflict-free LDS.128 reads),
// Vs [64][132], Ps [64][68]. 256 threads: tx = t&15, ty = t>>4.
//  S-phase: each thread computes a 4x4 score tile (rows ty*4.., cols tx*4..)
//  PV-phase: each thread owns rows ty*4.. x cols tx*8.. of the 64x128 O tile.
// Online softmax row reductions via 16-lane xor shuffles.
// ---------------------------------------------------------------------------
#define ATTN_SMEM_FLOATS (128*68 + 128*68 + 64*132 + 64*68)

__global__ __launch_bounds__(256)
void attn_flash(const float* __restrict__ q, const float* __restrict__ k,
                const float* __restrict__ v, float* __restrict__ o)
{
    extern __shared__ float sm[];
    float* Qt = sm;                 // [128][68]
    float* Kt = Qt + 128*68;        // [128][68]
    float* Vs = Kt + 128*68;        // [64][132]
    float* Ps = Vs + 64*132;        // [64][68]

    const int t  = threadIdx.x;
    const int tx = t & 15;
    const int ty = t >> 4;
    const int qt = blockIdx.x;          // q tile, 0..31
    const int b  = blockIdx.y >> 4;
    const int h  = blockIdx.y & 15;
    const int q0 = qt * 64;

    const size_t headoff = (size_t)b * SEQ * HID + (size_t)h * DK;
    const float* qb = q + headoff;
    const float* kb = k + headoff;
    const float* vb = v + headoff;

    // Load Q tile transposed: Qt[d][s]
    for (int l = t; l < 64*32; l += 256) {
        const int s  = l >> 5;
        const int d0 = (l & 31) << 2;
        float4 val = *(const float4*)(qb + (size_t)(q0 + s) * HID + d0);
        Qt[(d0+0)*68 + s] = val.x;
        Qt[(d0+1)*68 + s] = val.y;
        Qt[(d0+2)*68 + s] = val.z;
        Qt[(d0+3)*68 + s] = val.w;
    }

    float m_i[4], l_i[4], oacc[4][8];
    #pragma unroll
    for (int i = 0; i < 4; ++i) {
        m_i[i] = -1e30f; l_i[i] = 0.f;
        #pragma unroll
        for (int c = 0; c < 8; ++c) oacc[i][c] = 0.f;
    }
    const float scale = 0.088388347648318447f;  // 1/sqrt(128)

    for (int j = 0; j <= qt; ++j) {
        const int kbase = j * 64;
        __syncthreads();   // prior PV reads of Kt/Vs/Ps complete
        for (int l = t; l < 64*32; l += 256) {
            const int s  = l >> 5;
            const int d0 = (l & 31) << 2;
            float4 kv = *(const float4*)(kb + (size_t)(kbase + s) * HID + d0);
            Kt[(d0+0)*68 + s] = kv.x;
            Kt[(d0+1)*68 + s] = kv.y;
            Kt[(d0+2)*68 + s] = kv.z;
            Kt[(d0+3)*68 + s] = kv.w;
            float4 vv = *(const float4*)(vb + (size_t)(kbase + s) * HID + d0);
            *(float4*)&Vs[s*132 + d0] = vv;
        }
        __syncthreads();

        // S = Q K^T for this tile (4x4 per thread)
        float sacc[4][4];
        #pragma unroll
        for (int i = 0; i < 4; ++i)
            #pragma unroll
            for (int jj = 0; jj < 4; ++jj) sacc[i][jj] = 0.f;

        #pragma unroll 4
        for (int d = 0; d < 128; ++d) {
            float4 qv = *(const float4*)&Qt[d*68 + ty*4];
            float4 kv = *(const float4*)&Kt[d*68 + tx*4];
            float qr[4] = {qv.x,qv.y,qv.z,qv.w};
            float kr[4] = {kv.x,kv.y,kv.z,kv.w};
            #pragma unroll
            for (int i = 0; i < 4; ++i)
                #pragma unroll
                for (int jj = 0; jj < 4; ++jj)
                    sacc[i][jj] = fmaf(qr[i], kr[jj], sacc[i][jj]);
        }

        const bool diag = (j == qt);
        #pragma unroll
        for (int i = 0; i < 4; ++i) {
            float sv[4];
            #pragma unroll
            for (int jj = 0; jj < 4; ++jj) {
                float x = sacc[i][jj] * scale;
                if (diag && (tx*4 + jj > ty*4 + i)) x = -1e30f;  // causal
                sv[jj] = x;
            }
            float rm = fmaxf(fmaxf(sv[0], sv[1]), fmaxf(sv[2], sv[3]));
            #pragma unroll
            for (int off = 8; off > 0; off >>= 1)
                rm = fmaxf(rm, __shfl_xor_sync(0xffffffffu, rm, off, 16));
            const float mnew = fmaxf(m_i[i], rm);
            const float corr = __expf(m_i[i] - mnew);
            float rs = 0.f;
            const int prow = (ty*4 + i)*68 + tx*4;
            #pragma unroll
            for (int jj = 0; jj < 4; ++jj) {
                const float p = __expf(sv[jj] - mnew);
                Ps[prow + jj] = p;
                rs += p;
            }
            #pragma unroll
            for (int off = 8; off > 0; off >>= 1)
                rs += __shfl_xor_sync(0xffffffffu, rs, off, 16);
            l_i[i] = l_i[i] * corr + rs;
            m_i[i] = mnew;
            #pragma unroll
            for (int c = 0; c < 8; ++c) oacc[i][c] *= corr;
        }
        __syncthreads();   // Ps fully written

        // O += P @ V  (4 rows x 8 cols per thread)
        #pragma unroll 2
        for (int kk = 0; kk < 64; ++kk) {
            float4 v0 = *(const float4*)&Vs[kk*132 + tx*8];
            float4 v1 = *(const float4*)&Vs[kk*132 + tx*8 + 4];
            #pragma unroll
            for (int i = 0; i < 4; ++i) {
                const float pp = Ps[(ty*4 + i)*68 + kk];
                oacc[i][0] = fmaf(pp, v0.x, oacc[i][0]);
                oacc[i][1] = fmaf(pp, v0.y, oacc[i][1]);
                oacc[i][2] = fmaf(pp, v0.z, oacc[i][2]);
                oacc[i][3] = fmaf(pp, v0.w, oacc[i][3]);
                oacc[i][4] = fmaf(pp, v1.x, oacc[i][4]);
                oacc[i][5] = fmaf(pp, v1.y, oacc[i][5]);
                oacc[i][6] = fmaf(pp, v1.z, oacc[i][6]);
                oacc[i][7] = fmaf(pp, v1.w, oacc[i][7]);
            }
        }
    }

    // Normalize and write (B,S,H) with head offset
    #pragma unroll
    for (int i = 0; i < 4; ++i) {
        const float inv = 1.f / l_i[i];
        const int row = q0 + ty*4 + i;
        float* op = o + headoff + (size_t)row * HID + tx*8;
        *(float4*)(op)   = make_float4(oacc[i][0]*inv, oacc[i][1]*inv,
                                       oacc[i][2]*inv, oacc[i][3]*inv);
        *(float4*)(op+4) = make_float4(oacc[i][4]*inv, oacc[i][5]*inv,
                                       oacc[i][6]*inv, oacc[i][7]*inv);
    }
}

// ---------------------------------------------------------------------------
// Launch: QKV GEMMs (RoPE fused into Q/K epilogue) -> flash attn -> out proj.
// ---------------------------------------------------------------------------
extern "C" void kernel_launch(void* const* d_in, const int* in_sizes, int n_in,
                              void* d_out, int out_size)
{
    (void)in_sizes; (void)n_in; (void)out_size;
    const float* x  = (const float*)d_in[0];
    const float* fr = (const float*)d_in[1];
    const float* wq = (const float*)d_in[2];
    const float* wk = (const float*)d_in[3];
    const float* wv = (const float*)d_in[4];
    const float* wo = (const float*)d_in[5];
    float* out = (float*)d_out;

    float *gq, *gk, *gv, *gao;
    cudaGetSymbolAddress((void**)&gq,  g_q);
    cudaGetSymbolAddress((void**)&gk,  g_k);
    cudaGetSymbolAddress((void**)&gv,  g_v);
    cudaGetSymbolAddress((void**)&gao, g_ao);

    dim3 gg(HID/128, MROWS/128);   // (16, 32)
    sgemm_nt<<<gg, 256>>>(x, wq, gq, HID, HID, fr, 1);
    sgemm_nt<<<gg, 256>>>(x, wk, gk, HID, HID, fr, 1);
    sgemm_nt<<<gg, 256>>>(x, wv, gv, HID, HID, nullptr, 0);

    const int smem = ATTN_SMEM_FLOATS * (int)sizeof(float);  // 120,832 B
    cudaFuncSetAttribute(attn_flash, cudaFuncAttributeMaxDynamicSharedMemorySize, smem);
    attn_flash<<<dim3(SEQ/64, BATCH*NHEAD), 256, smem>>>(gq, gk, gv, gao);

    sgemm_nt<<<gg, 256>>>(gao, wo, out, HID, HID, nullptr, 0);
}

// round 4
// speedup vs baseline: 1.6071x; 1.6071x over previous
#include <cuda_runtime.h>
#include <cuda_bf16.h>

#define BATCH 2
#define SEQ   2048
#define HID   2048
#define NHEAD 16
#define DK    128
#define MROWS (BATCH*SEQ)

// ---------------- scratch (allocation-free) ----------------
__device__ __nv_bfloat16 g_x_hi[(size_t)MROWS * HID];
__device__ __nv_bfloat16 g_x_lo[(size_t)MROWS * HID];
__device__ __nv_bfloat16 g_w_hi[4][(size_t)HID * HID];
__device__ __nv_bfloat16 g_w_lo[4][(size_t)HID * HID];
__device__ float g_q [(size_t)MROWS * HID];
__device__ float g_k [(size_t)MROWS * HID];
__device__ float g_v [(size_t)MROWS * HID];
__device__ __nv_bfloat16 g_ao_hi[(size_t)MROWS * HID];
__device__ __nv_bfloat16 g_ao_lo[(size_t)MROWS * HID];

// ---------------- PTX helpers (all sm_80-era, no 'a'-gated ops) ----------------
__device__ __forceinline__ unsigned smem_u32(const void* p) {
    unsigned a;
    asm("{ .reg .u64 t; cvta.to.shared.u64 t, %1; cvt.u32.u64 %0, t; }" : "=r"(a) : "l"(p));
    return a;
}
__device__ __forceinline__ void cp16(unsigned s, const void* g) {
    asm volatile("cp.async.cg.shared.global [%0], [%1], 16;" :: "r"(s), "l"(g));
}
#define CP_COMMIT() asm volatile("cp.async.commit_group;" ::: "memory")
#define CP_WAIT(n)  asm volatile("cp.async.wait_group %0;" :: "n"(n) : "memory")

__device__ __forceinline__ void ldm4(unsigned* r, unsigned addr) {
    asm volatile("ldmatrix.sync.aligned.m8n8.x4.shared.b16 {%0,%1,%2,%3}, [%4];"
        : "=r"(r[0]), "=r"(r[1]), "=r"(r[2]), "=r"(r[3]) : "r"(addr));
}
__device__ __forceinline__ void mma_bf16(float* d, const unsigned* a, const unsigned* b) {
    asm volatile(
        "mma.sync.aligned.m16n8k16.row.col.f32.bf16.bf16.f32 "
        "{%0,%1,%2,%3}, {%4,%5,%6,%7}, {%8,%9}, {%0,%1,%2,%3};"
        : "+f"(d[0]), "+f"(d[1]), "+f"(d[2]), "+f"(d[3])
        : "r"(a[0]), "r"(a[1]), "r"(a[2]), "r"(a[3]), "r"(b[0]), "r"(b[1]));
}

// ---------------- fp32 -> bf16 hi/lo split ----------------
__global__ __launch_bounds__(256)
void split_bf16(const float* __restrict__ in, __nv_bfloat16* __restrict__ hi,
                __nv_bfloat16* __restrict__ lo, int n4)
{
    int i = blockIdx.x * 256 + threadIdx.x;
    if (i >= n4) return;
    float4 v = ((const float4*)in)[i];
    __nv_bfloat16 h0 = __float2bfloat16(v.x);
    __nv_bfloat16 h1 = __float2bfloat16(v.y);
    __nv_bfloat16 h2 = __float2bfloat16(v.z);
    __nv_bfloat16 h3 = __float2bfloat16(v.w);
    __nv_bfloat16 l0 = __float2bfloat16(v.x - __bfloat162float(h0));
    __nv_bfloat16 l1 = __float2bfloat16(v.y - __bfloat162float(h1));
    __nv_bfloat16 l2 = __float2bfloat16(v.z - __bfloat162float(h2));
    __nv_bfloat16 l3 = __float2bfloat16(v.w - __bfloat162float(h3));
    __nv_bfloat162* hp = (__nv_bfloat162*)hi;
    __nv_bfloat162* lp = (__nv_bfloat162*)lo;
    hp[2*i+0] = __nv_bfloat162(h0, h1);
    hp[2*i+1] = __nv_bfloat162(h2, h3);
    lp[2*i+0] = __nv_bfloat162(l0, l1);
    lp[2*i+1] = __nv_bfloat162(l2, l3);
}

// ---------------- mma.sync GEMM: C[m][n] = sum_k A[m][k] B[n][k] ----------------
// A = Ahi+Alo, B = Bhi+Blo (bf16); 3-product fp32 accumulation.
// 128x128 tile, BK=32, 8 warps (2m x 4n, warp tile 64x32), cp.async 2-stage.
// Smem rows padded to 80B: row stride 20 words => 8 consecutive rows cover
// disjoint bank quartets => conflict-free ldmatrix.
#define BKI 32
#define ROWB 80
#define ARR_BYTES (128 * ROWB)        // 10240
#define OFF_AHI 0
#define OFF_ALO (1 * ARR_BYTES)
#define OFF_BHI (2 * ARR_BYTES)
#define OFF_BLO (3 * ARR_BYTES)
#define STG_BYTES (4 * ARR_BYTES)     // 40960
#define GEMM_SMEM (2 * STG_BYTES)     // 81920
#define NKIT (HID / BKI)              // 64

__device__ __forceinline__ void gemm_load_stage(
    const __nv_bfloat16* __restrict__ Ahi, const __nv_bfloat16* __restrict__ Alo,
    const __nv_bfloat16* __restrict__ Bhi, const __nv_bfloat16* __restrict__ Blo,
    int rowBase, int colBase, int k0, unsigned stage, int t)
{
    const int r    = t >> 1;          // 0..127
    const int half = t & 1;           // chunk pair 0/1
    const size_t ga = (size_t)(rowBase + r) * HID + k0 + half * 16;
    const size_t gb = (size_t)(colBase + r) * HID + k0 + half * 16;
    const unsigned so = r * ROWB + half * 32;
    cp16(stage + OFF_AHI + so,      Ahi + ga);
    cp16(stage + OFF_AHI + so + 16, Ahi + ga + 8);
    cp16(stage + OFF_ALO + so,      Alo + ga);
    cp16(stage + OFF_ALO + so + 16, Alo + ga + 8);
    cp16(stage + OFF_BHI + so,      Bhi + gb);
    cp16(stage + OFF_BHI + so + 16, Bhi + gb + 8);
    cp16(stage + OFF_BLO + so,      Blo + gb);
    cp16(stage + OFF_BLO + so + 16, Blo + gb + 8);
}

__global__ __launch_bounds__(256)
void gemm_mma(const __nv_bfloat16* __restrict__ Ahi, const __nv_bfloat16* __restrict__ Alo,
              const __nv_bfloat16* __restrict__ Bhi, const __nv_bfloat16* __restrict__ Blo,
              float* __restrict__ C, const float* __restrict__ freqs, int do_rope)
{
    extern __shared__ char sm[];
    const unsigned smem = smem_u32(sm);
    const int t    = threadIdx.x;
    const int wid  = t >> 5;
    const int lane = t & 31;
    const int wm   = wid & 1;          // 0..1 (64-row groups)
    const int wn   = wid >> 1;         // 0..3 (32-col groups)
    const int rowBase = blockIdx.y * 128;
    const int colBase = blockIdx.x * 128;

    // ldmatrix per-lane base offsets (within an array, before ks/mt/pair strides)
    const unsigned aOff = (wm * 64 + (lane & 15)) * ROWB + ((lane >> 4) & 1) * 16;
    const unsigned bOff = (wn * 32 + ((lane >> 4) & 1) * 8 + (lane & 7)) * ROWB
                        + ((lane >> 3) & 1) * 16;

    float acc[4][4][4];
    #pragma unroll
    for (int mt = 0; mt < 4; ++mt)
        #pragma unroll
        for (int nt = 0; nt < 4; ++nt)
            #pragma unroll
            for (int c = 0; c < 4; ++c) acc[mt][nt][c] = 0.f;

    // prologue
    gemm_load_stage(Ahi, Alo, Bhi, Blo, rowBase, colBase, 0, smem, t);
    CP_COMMIT();

    for (int it = 0; it < NKIT; ++it) {
        const unsigned cur = smem + (it & 1) * STG_BYTES;
        if (it + 1 < NKIT) {
            gemm_load_stage(Ahi, Alo, Bhi, Blo, rowBase, colBase, (it + 1) * BKI,
                            smem + ((it + 1) & 1) * STG_BYTES, t);
            CP_COMMIT();
            CP_WAIT(1);
        } else {
            CP_WAIT(0);
        }
        __syncthreads();

        #pragma unroll
        for (int ks = 0; ks < 2; ++ks) {
            const unsigned kofs = ks * 32;
            unsigned ah[4][4], al[4][4], bh[2][4], bl[2][4];
            #pragma unroll
            for (int mt = 0; mt < 4; ++mt) {
                ldm4(ah[mt], cur + OFF_AHI + aOff + mt * (16 * ROWB) + kofs);
                ldm4(al[mt], cur + OFF_ALO + aOff + mt * (16 * ROWB) + kofs);
            }
            #pragma unroll
            for (int p = 0; p < 2; ++p) {
                ldm4(bh[p], cur + OFF_BHI + bOff + p * (16 * ROWB) + kofs);
                ldm4(bl[p], cur + OFF_BLO + bOff + p * (16 * ROWB) + kofs);
            }
            #pragma unroll
            for (int mt = 0; mt < 4; ++mt)
                #pragma unroll
                for (int nt = 0; nt < 4; ++nt) {
                    const unsigned* rbh = &bh[nt >> 1][(nt & 1) * 2];
                    const unsigned* rbl = &bl[nt >> 1][(nt & 1) * 2];
                    mma_bf16(acc[mt][nt], ah[mt], rbh);
                    mma_bf16(acc[mt][nt], ah[mt], rbl);
                    mma_bf16(acc[mt][nt], al[mt], rbh);
                }
        }
        __syncthreads();
    }

    // epilogue: lane holds rows (g, g+8), col pair tig*2 per tile
    const int g   = lane >> 2;
    const int tig = lane & 3;
    #pragma unroll
    for (int mt = 0; mt < 4; ++mt) {
        #pragma unroll
        for (int nt = 0; nt < 4; ++nt) {
            const int m0 = rowBase + wm * 64 + mt * 16 + g;
            const int n0 = colBase + wn * 32 + nt * 8 + tig * 2;
            float v0 = acc[mt][nt][0], v1 = acc[mt][nt][1];
            float v2 = acc[mt][nt][2], v3 = acc[mt][nt][3];
            if (do_rope) {
                const int d = n0 & (DK - 1);     // even
                const int s0 = m0 & (SEQ - 1);
                const int s1 = (m0 + 8) & (SEQ - 1);
                const float cs0 = freqs[s0 * DK + d], sn0 = freqs[s0 * DK + d + 1];
                const float cs1 = freqs[s1 * DK + d], sn1 = freqs[s1 * DK + d + 1];
                *(float2*)(C + (size_t)m0 * HID + n0) =
                    make_float2(v0 * cs0 - v1 * sn0, v0 * sn0 + v1 * cs0);
                *(float2*)(C + (size_t)(m0 + 8) * HID + n0) =
                    make_float2(v2 * cs1 - v3 * sn1, v2 * sn1 + v3 * cs1);
            } else {
                *(float2*)(C + (size_t)m0 * HID + n0)       = make_float2(v0, v1);
                *(float2*)(C + (size_t)(m0 + 8) * HID + n0) = make_float2(v2, v3);
            }
        }
    }
}

// ---------------------------------------------------------------------------
// Flash attention, fp32, causal (proven R1 kernel); epilogue emits bf16 hi/lo.
// ---------------------------------------------------------------------------
#define ATTN_SMEM_FLOATS (128*68 + 128*68 + 64*132 + 64*68)

__global__ __launch_bounds__(256)
void attn_flash(const float* __restrict__ q, const float* __restrict__ k,
                const float* __restrict__ v,
                __nv_bfloat16* __restrict__ ohi, __nv_bfloat16* __restrict__ olo)
{
    extern __shared__ float smf[];
    float* Qt = smf;                // [128][68]
    float* Kt = Qt + 128*68;        // [128][68]
    float* Vs = Kt + 128*68;        // [64][132]
    float* Ps = Vs + 64*132;        // [64][68]

    const int t  = threadIdx.x;
    const int tx = t & 15;
    const int ty = t >> 4;
    const int qt = blockIdx.x;
    const int b  = blockIdx.y >> 4;
    const int h  = blockIdx.y & 15;
    const int q0 = qt * 64;

    const size_t headoff = (size_t)b * SEQ * HID + (size_t)h * DK;
    const float* qb = q + headoff;
    const float* kb = k + headoff;
    const float* vb = v + headoff;

    for (int l = t; l < 64*32; l += 256) {
        const int s  = l >> 5;
        const int d0 = (l & 31) << 2;
        float4 val = *(const float4*)(qb + (size_t)(q0 + s) * HID + d0);
        Qt[(d0+0)*68 + s] = val.x;
        Qt[(d0+1)*68 + s] = val.y;
        Qt[(d0+2)*68 + s] = val.z;
        Qt[(d0+3)*68 + s] = val.w;
    }

    float m_i[4], l_i[4], oacc[4][8];
    #pragma unroll
    for (int i = 0; i < 4; ++i) {
        m_i[i] = -1e30f; l_i[i] = 0.f;
        #pragma unroll
        for (int c = 0; c < 8; ++c) oacc[i][c] = 0.f;
    }
    const float scale = 0.088388347648318447f;

    for (int j = 0; j <= qt; ++j) {
        const int kbase = j * 64;
        __syncthreads();
        for (int l = t; l < 64*32; l += 256) {
            const int s  = l >> 5;
            const int d0 = (l & 31) << 2;
            float4 kv = *(const float4*)(kb + (size_t)(kbase + s) * HID + d0);
            Kt[(d0+0)*68 + s] = kv.x;
            Kt[(d0+1)*68 + s] = kv.y;
            Kt[(d0+2)*68 + s] = kv.z;
            Kt[(d0+3)*68 + s] = kv.w;
            float4 vv = *(const float4*)(vb + (size_t)(kbase + s) * HID + d0);
            *(float4*)&Vs[s*132 + d0] = vv;
        }
        __syncthreads();

        float sacc[4][4];
        #pragma unroll
        for (int i = 0; i < 4; ++i)
            #pragma unroll
            for (int jj = 0; jj < 4; ++jj) sacc[i][jj] = 0.f;

        #pragma unroll 4
        for (int d = 0; d < 128; ++d) {
            float4 qv = *(const float4*)&Qt[d*68 + ty*4];
            float4 kv = *(const float4*)&Kt[d*68 + tx*4];
            float qr[4] = {qv.x,qv.y,qv.z,qv.w};
            float kr[4] = {kv.x,kv.y,kv.z,kv.w};
            #pragma unroll
            for (int i = 0; i < 4; ++i)
                #pragma unroll
                for (int jj = 0; jj < 4; ++jj)
                    sacc[i][jj] = fmaf(qr[i], kr[jj], sacc[i][jj]);
        }

        const bool diag = (j == qt);
        #pragma unroll
        for (int i = 0; i < 4; ++i) {
            float sv[4];
            #pragma unroll
            for (int jj = 0; jj < 4; ++jj) {
                float x = sacc[i][jj] * scale;
                if (diag && (tx*4 + jj > ty*4 + i)) x = -1e30f;
                sv[jj] = x;
            }
            float rm = fmaxf(fmaxf(sv[0], sv[1]), fmaxf(sv[2], sv[3]));
            #pragma unroll
            for (int off = 8; off > 0; off >>= 1)
                rm = fmaxf(rm, __shfl_xor_sync(0xffffffffu, rm, off, 16));
            const float mnew = fmaxf(m_i[i], rm);
            const float corr = __expf(m_i[i] - mnew);
            float rs = 0.f;
            const int prow = (ty*4 + i)*68 + tx*4;
            #pragma unroll
            for (int jj = 0; jj < 4; ++jj) {
                const float p = __expf(sv[jj] - mnew);
                Ps[prow + jj] = p;
                rs += p;
            }
            #pragma unroll
            for (int off = 8; off > 0; off >>= 1)
                rs += __shfl_xor_sync(0xffffffffu, rs, off, 16);
            l_i[i] = l_i[i] * corr + rs;
            m_i[i] = mnew;
            #pragma unroll
            for (int c = 0; c < 8; ++c) oacc[i][c] *= corr;
        }
        __syncthreads();

        #pragma unroll 2
        for (int kk = 0; kk < 64; ++kk) {
            float4 v0 = *(const float4*)&Vs[kk*132 + tx*8];
            float4 v1 = *(const float4*)&Vs[kk*132 + tx*8 + 4];
            #pragma unroll
            for (int i = 0; i < 4; ++i) {
                const float pp = Ps[(ty*4 + i)*68 + kk];
                oacc[i][0] = fmaf(pp, v0.x, oacc[i][0]);
                oacc[i][1] = fmaf(pp, v0.y, oacc[i][1]);
                oacc[i][2] = fmaf(pp, v0.z, oacc[i][2]);
                oacc[i][3] = fmaf(pp, v0.w, oacc[i][3]);
                oacc[i][4] = fmaf(pp, v1.x, oacc[i][4]);
                oacc[i][5] = fmaf(pp, v1.y, oacc[i][5]);
                oacc[i][6] = fmaf(pp, v1.z, oacc[i][6]);
                oacc[i][7] = fmaf(pp, v1.w, oacc[i][7]);
            }
        }
    }

    #pragma unroll
    for (int i = 0; i < 4; ++i) {
        const float inv = 1.f / l_i[i];
        const int row = q0 + ty*4 + i;
        const size_t idx = headoff + (size_t)row * HID + tx*8;
        __nv_bfloat162* hp = (__nv_bfloat162*)(ohi + idx);
        __nv_bfloat162* lp = (__nv_bfloat162*)(olo + idx);
        #pragma unroll
        for (int c = 0; c < 8; c += 2) {
            float a0 = oacc[i][c]   * inv;
            float a1 = oacc[i][c+1] * inv;
            __nv_bfloat16 h0 = __float2bfloat16(a0);
            __nv_bfloat16 h1 = __float2bfloat16(a1);
            __nv_bfloat16 l0 = __float2bfloat16(a0 - __bfloat162float(h0));
            __nv_bfloat16 l1 = __float2bfloat16(a1 - __bfloat162float(h1));
            hp[c >> 1] = __nv_bfloat162(h0, h1);
            lp[c >> 1] = __nv_bfloat162(l0, l1);
        }
    }
}

// ---------------------------------------------------------------------------
extern "C" void kernel_launch(void* const* d_in, const int* in_sizes, int n_in,
                              void* d_out, int out_size)
{
    (void)in_sizes; (void)n_in; (void)out_size;
    const float* x  = (const float*)d_in[0];
    const float* fr = (const float*)d_in[1];
    const float* w[4] = { (const float*)d_in[2], (const float*)d_in[3],
                          (const float*)d_in[4], (const float*)d_in[5] };
    float* out = (float*)d_out;

    __nv_bfloat16 *xhi, *xlo, *whi, *wlo, *aohi, *aolo;
    float *gq, *gk, *gv;
    cudaGetSymbolAddress((void**)&xhi,  g_x_hi);
    cudaGetSymbolAddress((void**)&xlo,  g_x_lo);
    cudaGetSymbolAddress((void**)&whi,  g_w_hi);
    cudaGetSymbolAddress((void**)&wlo,  g_w_lo);
    cudaGetSymbolAddress((void**)&gq,   g_q);
    cudaGetSymbolAddress((void**)&gk,   g_k);
    cudaGetSymbolAddress((void**)&gv,   g_v);
    cudaGetSymbolAddress((void**)&aohi, g_ao_hi);
    cudaGetSymbolAddress((void**)&aolo, g_ao_lo);

    cudaFuncSetAttribute(gemm_mma, cudaFuncAttributeMaxDynamicSharedMemorySize, GEMM_SMEM);
    cudaFuncSetAttribute(attn_flash, cudaFuncAttributeMaxDynamicSharedMemorySize,
                         ATTN_SMEM_FLOATS * (int)sizeof(float));

    {
        int n4 = (MROWS * HID) / 4;
        split_bf16<<<(n4 + 255) / 256, 256>>>(x, xhi, xlo, n4);
        int w4 = (HID * HID) / 4;
        for (int i = 0; i < 4; ++i)
            split_bf16<<<(w4 + 255) / 256, 256>>>(w[i], whi + (size_t)i * HID * HID,
                                                  wlo + (size_t)i * HID * HID, w4);
    }

    dim3 gg(HID / 128, MROWS / 128);   // (16, 32)
    gemm_mma<<<gg, 256, GEMM_SMEM>>>(xhi, xlo, whi + 0 * (size_t)HID * HID,
                                     wlo + 0 * (size_t)HID * HID, gq, fr, 1);
    gemm_mma<<<gg, 256, GEMM_SMEM>>>(xhi, xlo, whi + 1 * (size_t)HID * HID,
                                     wlo + 1 * (size_t)HID * HID, gk, fr, 1);
    gemm_mma<<<gg, 256, GEMM_SMEM>>>(xhi, xlo, whi + 2 * (size_t)HID * HID,
                                     wlo + 2 * (size_t)HID * HID, gv, nullptr, 0);

    attn_flash<<<dim3(SEQ / 64, BATCH * NHEAD), 256, ATTN_SMEM_FLOATS * (int)sizeof(float)>>>(
        gq, gk, gv, aohi, aolo);

    gemm_mma<<<gg, 256, GEMM_SMEM>>>(aohi, aolo, whi + 3 * (size_t)HID * HID,
                                     wlo + 3 * (size_t)HID * HID, out, nullptr, 0);
}